// round 1
// baseline (speedup 1.0000x reference)
#include <cuda_runtime.h>

#define B_ 16
#define C_ 64
#define H_ 128
#define W_ 128
#define NTOT (B_*C_*H_*W_)

// Scratch (allocation-free rule: __device__ globals)
__device__ float g_score[NTOT];
__device__ float g_gx[NTOT];
__device__ float g_gy[NTOT];

// Conv tiling
#define CI  8      // input-channel chunk staged in smem
#define RCO 16     // output channels per CTA pass
#define TH  32
#define TW  32

__global__ __launch_bounds__(256, 2)
void conv3_kernel(const float* __restrict__ xin,
                  const float* __restrict__ Ws, const float* __restrict__ bs,
                  const float* __restrict__ Wx, const float* __restrict__ bx,
                  const float* __restrict__ Wy, const float* __restrict__ by)
{
    __shared__ float s_in[CI][TH + 2][TW + 4];   // 8*34*36*4 = 39168 B
    __shared__ float s_w[CI][9][RCO];            // 8*9*16*4  =  4608 B

    const int tid = threadIdx.x;
    const int tx  = tid & 15;
    const int ty  = tid >> 4;
    const int x0  = blockIdx.x * TW;
    const int y0  = blockIdx.y * TH;
    const int zz  = blockIdx.z;
    const int co_pass = zz % 12;       // 12 passes of 16 channels over 192
    const int b       = zz / 12;
    const int set     = co_pass >> 2;  // 0:score 1:gx 2:gy
    const int c0      = (co_pass & 3) * RCO;

    const float* Wt = (set == 0) ? Ws : ((set == 1) ? Wx : Wy);
    const float* Bt = (set == 0) ? bs : ((set == 1) ? bx : by);
    float*     outp = (set == 0) ? g_score : ((set == 1) ? g_gx : g_gy);

    float acc[4][RCO];
    #pragma unroll
    for (int p = 0; p < 4; p++)
        #pragma unroll
        for (int c = 0; c < RCO; c++) acc[p][c] = 0.0f;

    const int lx = tx * 2;   // tile-local pixel coords of 2x2 quad origin
    const int ly = ty * 2;

    for (int ci0 = 0; ci0 < C_; ci0 += CI) {
        __syncthreads();
        // cooperative load: input tile (CI, 34, 34) with zero halo
        for (int idx = tid; idx < CI * 34 * 34; idx += 256) {
            int ci  = idx / (34 * 34);
            int rem = idx - ci * (34 * 34);
            int yy  = rem / 34;
            int xx  = rem - yy * 34;
            int gy  = y0 - 1 + yy;
            int gx  = x0 - 1 + xx;
            float v = 0.0f;
            if (gy >= 0 && gy < H_ && gx >= 0 && gx < W_)
                v = xin[(((size_t)b * C_ + ci0 + ci) * H_ + gy) * W_ + gx];
            s_in[ci][yy][xx] = v;
        }
        // cooperative load: weights, layout [ci][tap][co] so co is contiguous
        for (int idx = tid; idx < CI * 9 * RCO; idx += 256) {
            int co  = idx & (RCO - 1);
            int rem = idx >> 4;
            int tap = rem % 9;
            int ci  = rem / 9;
            s_w[ci][tap][co] = Wt[((size_t)(c0 + co) * C_ + ci0 + ci) * 9 + tap];
        }
        __syncthreads();

        for (int ci = 0; ci < CI; ci++) {
            // 4x4 input neighborhood covering the 2x2 quad's 3x3 taps
            float in[4][4];
            #pragma unroll
            for (int r = 0; r < 4; r++)
                #pragma unroll
                for (int c2 = 0; c2 < 4; c2++)
                    in[r][c2] = s_in[ci][ly + r][lx + c2];

            #pragma unroll
            for (int dy = 0; dy < 3; dy++) {
                #pragma unroll
                for (int dx = 0; dx < 3; dx++) {
                    const int tap = dy * 3 + dx;
                    float4 wa = *(const float4*)&s_w[ci][tap][0];
                    float4 wb = *(const float4*)&s_w[ci][tap][4];
                    float4 wc = *(const float4*)&s_w[ci][tap][8];
                    float4 wd = *(const float4*)&s_w[ci][tap][12];
                    float w[16] = { wa.x, wa.y, wa.z, wa.w,
                                    wb.x, wb.y, wb.z, wb.w,
                                    wc.x, wc.y, wc.z, wc.w,
                                    wd.x, wd.y, wd.z, wd.w };
                    #pragma unroll
                    for (int p = 0; p < 4; p++) {
                        const float iv = in[(p >> 1) + dy][(p & 1) + dx];
                        #pragma unroll
                        for (int c = 0; c < RCO; c++)
                            acc[p][c] = fmaf(iv, w[c], acc[p][c]);
                    }
                }
            }
        }
    }

    float biasv[RCO];
    #pragma unroll
    for (int c = 0; c < RCO; c++) biasv[c] = Bt[c0 + c];

    #pragma unroll
    for (int p = 0; p < 4; p++) {
        const int py = y0 + ly + (p >> 1);
        const int px = x0 + lx + (p & 1);
        #pragma unroll
        for (int c = 0; c < RCO; c++)
            outp[(((size_t)b * C_ + c0 + c) * H_ + py) * W_ + px] = acc[p][c] + biasv[c];
    }
}

// Bilinear grid sample, align_corners=False, padding_mode=zeros.
__global__ void sample_kernel(float* __restrict__ out)
{
    const int idx = blockIdx.x * blockDim.x + threadIdx.x;
    if (idx >= NTOT) return;
    const int n = idx >> 14;          // B*C image index (H*W = 16384)

    const float gx = g_gx[idx];
    const float gy = g_gy[idx];
    const float ix = ((gx + 1.0f) * (float)W_ - 1.0f) * 0.5f;
    const float iy = ((gy + 1.0f) * (float)H_ - 1.0f) * 0.5f;

    const float x0f = floorf(ix);
    const float y0f = floorf(iy);
    const int ix0 = (int)x0f, iy0 = (int)y0f;
    const int ix1 = ix0 + 1,  iy1 = iy0 + 1;
    const float wx1 = ix - x0f, wy1 = iy - y0f;
    const float wx0 = 1.0f - wx1, wy0 = 1.0f - wy1;

    const float* img = g_score + ((size_t)n << 14);
    float v = 0.0f;
    if ((unsigned)iy0 < H_ && (unsigned)ix0 < W_) v = fmaf(__ldg(&img[iy0 * W_ + ix0]), wy0 * wx0, v);
    if ((unsigned)iy0 < H_ && (unsigned)ix1 < W_) v = fmaf(__ldg(&img[iy0 * W_ + ix1]), wy0 * wx1, v);
    if ((unsigned)iy1 < H_ && (unsigned)ix0 < W_) v = fmaf(__ldg(&img[iy1 * W_ + ix0]), wy1 * wx0, v);
    if ((unsigned)iy1 < H_ && (unsigned)ix1 < W_) v = fmaf(__ldg(&img[iy1 * W_ + ix1]), wy1 * wx1, v);

    out[idx] = v;
}

extern "C" void kernel_launch(void* const* d_in, const int* in_sizes, int n_in,
                              void* d_out, int out_size)
{
    const float* x  = (const float*)d_in[0];
    const float* Ws = (const float*)d_in[1];
    const float* bs = (const float*)d_in[2];
    const float* Wx = (const float*)d_in[3];
    const float* bx = (const float*)d_in[4];
    const float* Wy = (const float*)d_in[5];
    const float* by = (const float*)d_in[6];
    float* out = (float*)d_out;

    dim3 grid(W_ / TW, H_ / TH, B_ * 12);
    conv3_kernel<<<grid, 256>>>(x, Ws, bs, Wx, bx, Wy, by);
    sample_kernel<<<(NTOT + 255) / 256, 256>>>(out);
}

// round 5
// speedup vs baseline: 1.1277x; 1.1277x over previous
#include <cuda_runtime.h>
#include <cstdint>

#define B_ 16
#define C_ 64
#define H_ 128
#define W_ 128
#define NTOT (B_*C_*H_*W_)
#define NOUT 192
#define KTOT 576
#define KC   32
#define NCHUNK (KTOT/KC)   /* 18 */

// ---- scratch (allocation-free rule: __device__ globals) ----
__device__ float g_score[NTOT];
__device__ float g_gx[NTOT];
__device__ float g_gy[NTOT];
__device__ float g_xh[NTOT];
__device__ float g_xl[NTOT];
__device__ float g_Bh[NOUT * KTOT];
__device__ float g_Bl[NOUT * KTOT];
__device__ float g_bias[NOUT];

// smem float offsets (stride 36 = 32 + 4 pad -> conflict-free fragment LDS)
#define AS 36
#define OFF_AH 0
#define OFF_AL (128 * AS)
#define OFF_BH (2 * 128 * AS)
#define OFF_BL (2 * 128 * AS + 192 * AS)
#define SMEM_FLOATS (2 * 128 * AS + 2 * 192 * AS)   /* 23040 floats = 92160 B */

__device__ __forceinline__ float tf32_rn(float a) {
    uint32_t u;
    asm("cvt.rna.tf32.f32 %0, %1;" : "=r"(u) : "f"(a));
    return __uint_as_float(u);
}

__device__ __forceinline__ void mma8(float* d, const uint32_t* a, const uint32_t* b) {
    asm volatile(
        "mma.sync.aligned.m16n8k8.row.col.f32.tf32.tf32.f32 "
        "{%0,%1,%2,%3}, {%4,%5,%6,%7}, {%8,%9}, {%0,%1,%2,%3};"
        : "+f"(d[0]), "+f"(d[1]), "+f"(d[2]), "+f"(d[3])
        : "r"(a[0]), "r"(a[1]), "r"(a[2]), "r"(a[3]), "r"(b[0]), "r"(b[1]));
}

// ---- precompute: tf32 hi/lo split of x and weights ----
__global__ void split_x_kernel(const float* __restrict__ x) {
    int i = (blockIdx.x * blockDim.x + threadIdx.x) * 4;
    if (i < NTOT) {
        float4 v = *(const float4*)&x[i];
        float h0 = tf32_rn(v.x), h1 = tf32_rn(v.y), h2 = tf32_rn(v.z), h3 = tf32_rn(v.w);
        *(float4*)&g_xh[i] = make_float4(h0, h1, h2, h3);
        *(float4*)&g_xl[i] = make_float4(tf32_rn(v.x - h0), tf32_rn(v.y - h1),
                                         tf32_rn(v.z - h2), tf32_rn(v.w - h3));
    }
}

__global__ void prep_w_kernel(const float* __restrict__ Ws, const float* __restrict__ bs,
                              const float* __restrict__ Wx, const float* __restrict__ bx,
                              const float* __restrict__ Wy, const float* __restrict__ by) {
    int idx = blockIdx.x * blockDim.x + threadIdx.x;
    if (idx < NOUT * KTOT) {
        int n = idx / KTOT, k = idx - n * KTOT;
        int set = n >> 6, co = n & 63;
        int ci = k / 9, tap = k - ci * 9;
        const float* Wt = (set == 0) ? Ws : ((set == 1) ? Wx : Wy);
        float w = Wt[(co * 64 + ci) * 9 + tap];
        float h = tf32_rn(w);
        g_Bh[idx] = h;
        g_Bl[idx] = tf32_rn(w - h);
    }
    if (idx < NOUT) {
        int set = idx >> 6, co = idx & 63;
        const float* Bt = (set == 0) ? bs : ((set == 1) ? bx : by);
        g_bias[idx] = Bt[co];
    }
}

// ---- conv GEMM: one CTA = one (b, y). M=128 px, N=192 ch, K=576 ----
__global__ __launch_bounds__(256, 1)
void conv_mma_kernel() {
    extern __shared__ float smem[];
    const int tid = threadIdx.x;
    const int wid = tid >> 5;
    const int lane = tid & 31;
    const int b = blockIdx.x >> 7;
    const int y = blockIdx.x & 127;

    const int mbase = (wid >> 2) * 64;   // warp M origin (2 rows of warps)
    const int nbase = (wid & 3) * 48;    // warp N origin (4 cols of warps)

    float acc[4][6][4];
    #pragma unroll
    for (int mt = 0; mt < 4; mt++)
        #pragma unroll
        for (int nt = 0; nt < 6; nt++)
            #pragma unroll
            for (int r = 0; r < 4; r++) acc[mt][nt][r] = 0.0f;

    const int lr = lane >> 2;   // fragment row-within-8
    const int lc = lane & 3;    // fragment col-within-4

    for (int c = 0; c < NCHUNK; c++) {
        const int k0 = c * KC;
        __syncthreads();

        // stage A (im2col, hi+lo): 128 m x 8 k-quads
        #pragma unroll 1
        for (int idx = tid; idx < 1024; idx += 256) {
            const int m = idx & 127;
            const int kq = idx >> 7;
            float vh[4], vl[4];
            #pragma unroll
            for (int j = 0; j < 4; j++) {
                const int k = k0 + kq * 4 + j;
                const int ci = k / 9, tap = k - ci * 9;
                const int dy = tap / 3, dx = tap - dy * 3;
                const int yy = y + dy - 1, xx = m + dx - 1;
                const bool ok = ((unsigned)yy < 128u) & ((unsigned)xx < 128u);
                const int yc = ok ? yy : 0, xc = ok ? xx : 0;
                const int gi = ((b * 64 + ci) << 14) + (yc << 7) + xc;
                const float h = g_xh[gi], l = g_xl[gi];
                vh[j] = ok ? h : 0.0f;
                vl[j] = ok ? l : 0.0f;
            }
            const int off = m * AS + kq * 4;
            *(float4*)&smem[OFF_AH + off] = make_float4(vh[0], vh[1], vh[2], vh[3]);
            *(float4*)&smem[OFF_AL + off] = make_float4(vl[0], vl[1], vl[2], vl[3]);
        }

        // stage B (weights, hi+lo): 192 n x 8 k-quads
        #pragma unroll 1
        for (int idx = tid; idx < 1536; idx += 256) {
            const int n = idx >> 3;
            const int k4 = idx & 7;
            const int ga = n * KTOT + k0 + k4 * 4;
            float4 vh = *(const float4*)&g_Bh[ga];
            float4 vl = *(const float4*)&g_Bl[ga];
            const int off = n * AS + k4 * 4;
            *(float4*)&smem[OFF_BH + off] = vh;
            *(float4*)&smem[OFF_BL + off] = vl;
        }

        __syncthreads();

        #pragma unroll
        for (int ks = 0; ks < 4; ks++) {
            const int kk = ks * 8;
            uint32_t Ah[4][4], Al[4][4], Bh[6][2], Bl[6][2];
            #pragma unroll
            for (int mt = 0; mt < 4; mt++) {
                const int r0 = (mbase + mt * 16 + lr) * AS + kk + lc;
                Ah[mt][0] = __float_as_uint(smem[OFF_AH + r0]);
                Ah[mt][1] = __float_as_uint(smem[OFF_AH + r0 + 8 * AS]);
                Ah[mt][2] = __float_as_uint(smem[OFF_AH + r0 + 4]);
                Ah[mt][3] = __float_as_uint(smem[OFF_AH + r0 + 8 * AS + 4]);
                Al[mt][0] = __float_as_uint(smem[OFF_AL + r0]);
                Al[mt][1] = __float_as_uint(smem[OFF_AL + r0 + 8 * AS]);
                Al[mt][2] = __float_as_uint(smem[OFF_AL + r0 + 4]);
                Al[mt][3] = __float_as_uint(smem[OFF_AL + r0 + 8 * AS + 4]);
            }
            #pragma unroll
            for (int nt = 0; nt < 6; nt++) {
                const int r0 = (nbase + nt * 8 + lr) * AS + kk + lc;
                Bh[nt][0] = __float_as_uint(smem[OFF_BH + r0]);
                Bh[nt][1] = __float_as_uint(smem[OFF_BH + r0 + 4]);
                Bl[nt][0] = __float_as_uint(smem[OFF_BL + r0]);
                Bl[nt][1] = __float_as_uint(smem[OFF_BL + r0 + 4]);
            }
            #pragma unroll
            for (int mt = 0; mt < 4; mt++)
                #pragma unroll
                for (int nt = 0; nt < 6; nt++) {
                    mma8(acc[mt][nt], Ah[mt], Bh[nt]);   // hh
                    mma8(acc[mt][nt], Ah[mt], Bl[nt]);   // hl
                    mma8(acc[mt][nt], Al[mt], Bh[nt]);   // lh
                }
        }
    }

    // epilogue: direct scattered stores with bias
    #pragma unroll
    for (int nt = 0; nt < 6; nt++) {
        const int n0 = nbase + nt * 8 + 2 * lc;
        const int set0 = n0 >> 6, co0 = n0 & 63;
        const int set1 = (n0 + 1) >> 6, co1 = (n0 + 1) & 63;
        float* op0 = (set0 == 0) ? g_score : ((set0 == 1) ? g_gx : g_gy);
        float* op1 = (set1 == 0) ? g_score : ((set1 == 1) ? g_gx : g_gy);
        const float bias0 = __ldg(&g_bias[n0]);
        const float bias1 = __ldg(&g_bias[n0 + 1]);
        #pragma unroll
        for (int mt = 0; mt < 4; mt++) {
            const int m0 = mbase + mt * 16 + lr;
            const int a0 = ((b * 64 + co0) << 14) + (y << 7);
            const int a1 = ((b * 64 + co1) << 14) + (y << 7);
            op0[a0 + m0]     = acc[mt][nt][0] + bias0;
            op1[a1 + m0]     = acc[mt][nt][1] + bias1;
            op0[a0 + m0 + 8] = acc[mt][nt][2] + bias0;
            op1[a1 + m0 + 8] = acc[mt][nt][3] + bias1;
        }
    }
}

// ---- bilinear grid sample (align_corners=False, zeros padding) ----
__global__ void sample_kernel(float* __restrict__ out) {
    const int idx = blockIdx.x * blockDim.x + threadIdx.x;
    if (idx >= NTOT) return;
    const int n = idx >> 14;

    const float gx = g_gx[idx];
    const float gy = g_gy[idx];
    const float ix = ((gx + 1.0f) * (float)W_ - 1.0f) * 0.5f;
    const float iy = ((gy + 1.0f) * (float)H_ - 1.0f) * 0.5f;

    const float x0f = floorf(ix);
    const float y0f = floorf(iy);
    const int ix0 = (int)x0f, iy0 = (int)y0f;
    const int ix1 = ix0 + 1, iy1 = iy0 + 1;
    const float wx1 = ix - x0f, wy1 = iy - y0f;
    const float wx0 = 1.0f - wx1, wy0 = 1.0f - wy1;

    const float* img = g_score + ((size_t)n << 14);
    float v = 0.0f;
    if ((unsigned)iy0 < H_ && (unsigned)ix0 < W_) v = fmaf(__ldg(&img[iy0 * W_ + ix0]), wy0 * wx0, v);
    if ((unsigned)iy0 < H_ && (unsigned)ix1 < W_) v = fmaf(__ldg(&img[iy0 * W_ + ix1]), wy0 * wx1, v);
    if ((unsigned)iy1 < H_ && (unsigned)ix0 < W_) v = fmaf(__ldg(&img[iy1 * W_ + ix0]), wy1 * wx0, v);
    if ((unsigned)iy1 < H_ && (unsigned)ix1 < W_) v = fmaf(__ldg(&img[iy1 * W_ + ix1]), wy1 * wx1, v);

    out[idx] = v;
}

extern "C" void kernel_launch(void* const* d_in, const int* in_sizes, int n_in,
                              void* d_out, int out_size) {
    const float* x  = (const float*)d_in[0];
    const float* Ws = (const float*)d_in[1];
    const float* bs = (const float*)d_in[2];
    const float* Wx = (const float*)d_in[3];
    const float* bx = (const float*)d_in[4];
    const float* Wy = (const float*)d_in[5];
    const float* by = (const float*)d_in[6];
    float* out = (float*)d_out;

    cudaFuncSetAttribute(conv_mma_kernel,
                         cudaFuncAttributeMaxDynamicSharedMemorySize,
                         SMEM_FLOATS * sizeof(float));

    split_x_kernel<<<NTOT / 4 / 256, 256>>>(x);
    prep_w_kernel<<<(NOUT * KTOT + 255) / 256, 256>>>(Ws, bs, Wx, bx, Wy, by);
    conv_mma_kernel<<<B_ * H_, 256, SMEM_FLOATS * sizeof(float)>>>();
    sample_kernel<<<(NTOT + 255) / 256, 256>>>(out);
}

// round 6
// speedup vs baseline: 3.7496x; 3.3249x over previous
#include <cuda_runtime.h>
#include <cuda_fp16.h>
#include <cstdint>

#define B_ 16
#define C_ 64
#define H_ 128
#define W_ 128
#define NTOT (B_*C_*H_*W_)
#define NOUT 192
#define WSCALE 16.0f
#define WSCALE_INV 0.0625f

// ---- scratch (allocation-free rule: __device__ globals) ----
__device__ float  g_score[NTOT];
__device__ float  g_gx[NTOT];
__device__ float  g_gy[NTOT];
__device__ __half g_xh16[NTOT];          // NHWC: [b][y][x][ci]
__device__ __half g_xl16[NTOT];
__device__ __half g_B16h[9 * NOUT * 64]; // [tap][n][ci], scaled x16
__device__ __half g_B16l[9 * NOUT * 64];
__device__ float  g_bias[NOUT];

// ---- conv smem layout (halves) ----
// A tiles: [dy 0..2][xrow 0..131][ci 0..71], rows 0..129 used, stride 72 halves (144B)
#define ARS   72
#define APLN  (132 * ARS)                 /* 9504 halves per dy-plane */
#define OFF_AH 0
#define OFF_AL (3 * APLN)                 /* 28512 */
#define OFF_B  (6 * APLN)                 /* 57024 */
#define BTS    (NOUT * ARS)               /* 13824 halves per B tile */
// B[buf][hl]: OFF_B + (buf*2+hl)*BTS
#define SMEM_HALVES (OFF_B + 4 * BTS)     /* 112320 halves = 224640 B */
#define SMEM_BYTES  (SMEM_HALVES * 2)

// ---- fp16 m16n8k16 mma, fp32 accum ----
__device__ __forceinline__ void mma16(float* d, const uint32_t* a, const uint32_t* b) {
    asm volatile(
        "mma.sync.aligned.m16n8k16.row.col.f32.f16.f16.f32 "
        "{%0,%1,%2,%3}, {%4,%5,%6,%7}, {%8,%9}, {%0,%1,%2,%3};"
        : "+f"(d[0]), "+f"(d[1]), "+f"(d[2]), "+f"(d[3])
        : "r"(a[0]), "r"(a[1]), "r"(a[2]), "r"(a[3]), "r"(b[0]), "r"(b[1]));
}

// ---- split x to fp16 h/l and transpose NCHW -> NHWC ----
__global__ __launch_bounds__(256)
void split_x_kernel(const float* __restrict__ x) {
    __shared__ float tile[64 * 129];
    const int b = blockIdx.x >> 7;
    const int y = blockIdx.x & 127;
    const int tid = threadIdx.x;

    // read: coalesced over x, one (ci,y) row at a time
    for (int i = 0; i < 32; i++) {
        const int idx = i * 256 + tid;          // (ci, xx)
        const int ci = idx >> 7, xx = idx & 127;
        tile[ci * 129 + xx] = x[(((b * 64 + ci) << 7) + y << 7) + xx];
    }
    __syncthreads();
    // write: lanes over ci (conflict-free LDS: stride 129 floats)
    for (int i = 0; i < 32; i++) {
        const int idx = i * 256 + tid;          // (xx, ci)
        const int ci = idx & 63, xx = idx >> 6;
        const float v = tile[ci * 129 + xx];
        const __half h = __float2half(v);
        const __half l = __float2half(v - __half2float(h));
        const int o = (((b << 7) + y << 7) + xx << 6) + ci;
        g_xh16[o] = h;
        g_xl16[o] = l;
    }
}

// ---- prep weights: [tap][n][ci], scaled x16, fp16 h/l split ----
__global__ __launch_bounds__(256)
void prep_w_kernel(const float* __restrict__ Ws, const float* __restrict__ bs,
                   const float* __restrict__ Wx, const float* __restrict__ bx,
                   const float* __restrict__ Wy, const float* __restrict__ by) {
    const int idx = blockIdx.x * blockDim.x + threadIdx.x;
    if (idx < 9 * NOUT * 64) {
        const int tap = idx / (NOUT * 64);
        const int rem = idx - tap * (NOUT * 64);
        const int n = rem >> 6, ci = rem & 63;
        const int set = n >> 6, co = n & 63;
        const float* Wt = (set == 0) ? Ws : ((set == 1) ? Wx : Wy);
        const float w = Wt[(co * 64 + ci) * 9 + tap] * WSCALE;
        const __half h = __float2half(w);
        g_B16h[idx] = h;
        g_B16l[idx] = __float2half(w - __half2float(h));
    }
    if (idx < NOUT) {
        const int set = idx >> 6, co = idx & 63;
        const float* Bt = (set == 0) ? bs : ((set == 1) ? bx : by);
        g_bias[idx] = Bt[co];
    }
}

// ---- conv GEMM: CTA = (b, y). M=128 px (x), N=192 ch, K = 9 taps x 64 ci ----
__global__ __launch_bounds__(256, 1)
void conv_mma_kernel() {
    extern __shared__ __half smem[];
    const int tid = threadIdx.x;
    const int wid = tid >> 5;
    const int lane = tid & 31;
    const int b = blockIdx.x >> 7;
    const int y = blockIdx.x & 127;

    const int mbase = (wid >> 2) * 64;
    const int nbase = (wid & 3) * 48;
    const int lr = lane >> 2;
    const int lc = lane & 3;

    float acc[4][6][4];
    #pragma unroll
    for (int mt = 0; mt < 4; mt++)
        #pragma unroll
        for (int nt = 0; nt < 6; nt++)
            #pragma unroll
            for (int r = 0; r < 4; r++) acc[mt][nt][r] = 0.0f;

    // ---- stage A: 3 input rows (y-1..y+1), x_in -1..128 -> rows 0..129, all ci ----
    // vector chunks: (dy, xr 0..129, ci8 0..7) = 3120
    #pragma unroll 1
    for (int idx = tid; idx < 3120; idx += 256) {
        const int dy = idx / 1040;
        const int rem = idx - dy * 1040;
        const int xr = rem >> 3;            // 0..129
        const int ci8 = rem & 7;
        const int y_in = y + dy - 1;
        const int x_in = xr - 1;
        float4 vh = make_float4(0.f, 0.f, 0.f, 0.f);
        float4 vl = vh;
        if ((unsigned)y_in < 128u && (unsigned)x_in < 128u) {
            const int o = ((((b << 7) + y_in << 7) + x_in) << 6) + ci8 * 8;
            vh = *(const float4*)&g_xh16[o];
            vl = *(const float4*)&g_xl16[o];
        }
        const int so = dy * APLN + xr * ARS + ci8 * 8;
        *(float4*)&smem[OFF_AH + so] = vh;
        *(float4*)&smem[OFF_AL + so] = vl;
    }

    // ---- stage B tap 0 into buf 0 ----
    #pragma unroll 1
    for (int idx = tid; idx < 1536; idx += 256) {   // (n, ci8)
        const int n = idx >> 3, ci8 = idx & 7;
        const int go = (n << 6) + ci8 * 8;          // tap 0
        const int so = n * ARS + ci8 * 8;
        *(float4*)&smem[OFF_B + so]       = *(const float4*)&g_B16h[go];
        *(float4*)&smem[OFF_B + BTS + so] = *(const float4*)&g_B16l[go];
    }
    __syncthreads();

    #pragma unroll 1
    for (int tap = 0; tap < 9; tap++) {
        const int buf = tap & 1;
        // prefetch next tap's B into other buffer (overlaps with mma below)
        if (tap < 8) {
            const int nb = (tap + 1) & 1;
            const int gbase = (tap + 1) * NOUT * 64;
            #pragma unroll 1
            for (int idx = tid; idx < 1536; idx += 256) {
                const int n = idx >> 3, ci8 = idx & 7;
                const int go = gbase + (n << 6) + ci8 * 8;
                const int so = (nb * 2) * BTS + n * ARS + ci8 * 8;
                *(float4*)&smem[OFF_B + so]       = *(const float4*)&g_B16h[go];
                *(float4*)&smem[OFF_B + BTS + so] = *(const float4*)&g_B16l[go];
            }
        }

        const int dy = tap / 3;
        const int dx = tap - dy * 3;
        const int abase = dy * APLN;
        const int bbase = OFF_B + (buf * 2) * BTS;

        #pragma unroll
        for (int ks = 0; ks < 4; ks++) {
            const int kk = ks * 16 + 2 * lc;
            uint32_t Ah[4][4], Al[4][4], Bh[6][2], Bl[6][2];
            #pragma unroll
            for (int mt = 0; mt < 4; mt++) {
                const int r = abase + (mbase + mt * 16 + lr + dx) * ARS + kk;
                Ah[mt][0] = *(const uint32_t*)&smem[OFF_AH + r];
                Ah[mt][1] = *(const uint32_t*)&smem[OFF_AH + r + 8 * ARS];
                Ah[mt][2] = *(const uint32_t*)&smem[OFF_AH + r + 8];
                Ah[mt][3] = *(const uint32_t*)&smem[OFF_AH + r + 8 * ARS + 8];
                Al[mt][0] = *(const uint32_t*)&smem[OFF_AL + r];
                Al[mt][1] = *(const uint32_t*)&smem[OFF_AL + r + 8 * ARS];
                Al[mt][2] = *(const uint32_t*)&smem[OFF_AL + r + 8];
                Al[mt][3] = *(const uint32_t*)&smem[OFF_AL + r + 8 * ARS + 8];
            }
            #pragma unroll
            for (int nt = 0; nt < 6; nt++) {
                const int r = (nbase + nt * 8 + lr) * ARS + kk;
                Bh[nt][0] = *(const uint32_t*)&smem[bbase + r];
                Bh[nt][1] = *(const uint32_t*)&smem[bbase + r + 8];
                Bl[nt][0] = *(const uint32_t*)&smem[bbase + BTS + r];
                Bl[nt][1] = *(const uint32_t*)&smem[bbase + BTS + r + 8];
            }
            // independent streams: hh, then hl, then lh (no back-to-back RAW on same acc)
            #pragma unroll
            for (int mt = 0; mt < 4; mt++)
                #pragma unroll
                for (int nt = 0; nt < 6; nt++) mma16(acc[mt][nt], Ah[mt], Bh[nt]);
            #pragma unroll
            for (int mt = 0; mt < 4; mt++)
                #pragma unroll
                for (int nt = 0; nt < 6; nt++) mma16(acc[mt][nt], Ah[mt], Bl[nt]);
            #pragma unroll
            for (int mt = 0; mt < 4; mt++)
                #pragma unroll
                for (int nt = 0; nt < 6; nt++) mma16(acc[mt][nt], Al[mt], Bh[nt]);
        }
        __syncthreads();
    }

    // ---- epilogue: unscale, add bias, scattered stores ----
    #pragma unroll
    for (int nt = 0; nt < 6; nt++) {
        const int n0 = nbase + nt * 8 + 2 * lc;
        const int set0 = n0 >> 6, co0 = n0 & 63;
        const int set1 = (n0 + 1) >> 6, co1 = (n0 + 1) & 63;
        float* op0 = (set0 == 0) ? g_score : ((set0 == 1) ? g_gx : g_gy);
        float* op1 = (set1 == 0) ? g_score : ((set1 == 1) ? g_gx : g_gy);
        const float bias0 = __ldg(&g_bias[n0]);
        const float bias1 = __ldg(&g_bias[n0 + 1]);
        #pragma unroll
        for (int mt = 0; mt < 4; mt++) {
            const int m0 = mbase + mt * 16 + lr;
            const int a0 = ((b * 64 + co0) << 14) + (y << 7);
            const int a1 = ((b * 64 + co1) << 14) + (y << 7);
            op0[a0 + m0]     = acc[mt][nt][0] * WSCALE_INV + bias0;
            op1[a1 + m0]     = acc[mt][nt][1] * WSCALE_INV + bias1;
            op0[a0 + m0 + 8] = acc[mt][nt][2] * WSCALE_INV + bias0;
            op1[a1 + m0 + 8] = acc[mt][nt][3] * WSCALE_INV + bias1;
        }
    }
}

// ---- bilinear grid sample (align_corners=False, zeros padding) ----
__global__ void sample_kernel(float* __restrict__ out) {
    const int idx = blockIdx.x * blockDim.x + threadIdx.x;
    if (idx >= NTOT) return;
    const int n = idx >> 14;

    const float gx = g_gx[idx];
    const float gy = g_gy[idx];
    const float ix = ((gx + 1.0f) * (float)W_ - 1.0f) * 0.5f;
    const float iy = ((gy + 1.0f) * (float)H_ - 1.0f) * 0.5f;

    const float x0f = floorf(ix);
    const float y0f = floorf(iy);
    const int ix0 = (int)x0f, iy0 = (int)y0f;
    const int ix1 = ix0 + 1, iy1 = iy0 + 1;
    const float wx1 = ix - x0f, wy1 = iy - y0f;
    const float wx0 = 1.0f - wx1, wy0 = 1.0f - wy1;

    const float* img = g_score + ((size_t)n << 14);
    float v = 0.0f;
    if ((unsigned)iy0 < H_ && (unsigned)ix0 < W_) v = fmaf(__ldg(&img[iy0 * W_ + ix0]), wy0 * wx0, v);
    if ((unsigned)iy0 < H_ && (unsigned)ix1 < W_) v = fmaf(__ldg(&img[iy0 * W_ + ix1]), wy0 * wx1, v);
    if ((unsigned)iy1 < H_ && (unsigned)ix0 < W_) v = fmaf(__ldg(&img[iy1 * W_ + ix0]), wy1 * wx0, v);
    if ((unsigned)iy1 < H_ && (unsigned)ix1 < W_) v = fmaf(__ldg(&img[iy1 * W_ + ix1]), wy1 * wx1, v);

    out[idx] = v;
}

extern "C" void kernel_launch(void* const* d_in, const int* in_sizes, int n_in,
                              void* d_out, int out_size) {
    const float* x  = (const float*)d_in[0];
    const float* Ws = (const float*)d_in[1];
    const float* bs = (const float*)d_in[2];
    const float* Wx = (const float*)d_in[3];
    const float* bx = (const float*)d_in[4];
    const float* Wy = (const float*)d_in[5];
    const float* by = (const float*)d_in[6];
    float* out = (float*)d_out;

    cudaFuncSetAttribute(conv_mma_kernel,
                         cudaFuncAttributeMaxDynamicSharedMemorySize, SMEM_BYTES);

    split_x_kernel<<<B_ * H_, 256>>>(x);
    prep_w_kernel<<<(9 * NOUT * 64 + 255) / 256, 256>>>(Ws, bs, Wx, bx, Wy, by);
    conv_mma_kernel<<<B_ * H_, 256, SMEM_BYTES>>>();
    sample_kernel<<<(NTOT + 255) / 256, 256>>>(out);
}

// round 7
// speedup vs baseline: 4.3816x; 1.1686x over previous
#include <cuda_runtime.h>
#include <cuda_fp16.h>
#include <cstdint>

#define B_ 16
#define C_ 64
#define H_ 128
#define W_ 128
#define NTOT (B_*C_*H_*W_)
#define NOUT 192
#define WSCALE 16.0f
#define WSCALE_INV 0.0625f

// ---- scratch (allocation-free rule: __device__ globals) ----
__device__ float  g_score[NTOT];
__device__ float  g_gx[NTOT];
__device__ float  g_gy[NTOT];
__device__ __half g_xh16[NTOT];          // NHWC: [b][y][x][ci]
__device__ __half g_xl16[NTOT];
__device__ __half g_B16h[9 * NOUT * 64]; // [tap][n][ci], scaled x16
__device__ __half g_B16l[9 * NOUT * 64];
__device__ float  g_bias[NOUT];

// ---- conv smem layout (halves) ----
#define ARS   72
#define APLN  (132 * ARS)
#define OFF_AH 0
#define OFF_AL (3 * APLN)
#define OFF_B  (6 * APLN)
#define BTS    (NOUT * ARS)
#define SMEM_HALVES (OFF_B + 4 * BTS)     /* 112320 halves = 224640 B */
#define SMEM_BYTES  (SMEM_HALVES * 2)

__device__ __forceinline__ uint32_t smem_addr(const void* p) {
    return (uint32_t)__cvta_generic_to_shared(p);
}

#define CP_ASYNC16(dst, src) \
    asm volatile("cp.async.cg.shared.global [%0], [%1], 16;" :: "r"(dst), "l"(src) : "memory")
#define CP_COMMIT() asm volatile("cp.async.commit_group;" ::: "memory")
#define CP_WAIT0()  asm volatile("cp.async.wait_group 0;" ::: "memory")

__device__ __forceinline__ void ldsm_x4(uint32_t* r, uint32_t addr) {
    asm volatile("ldmatrix.sync.aligned.m8n8.x4.shared.b16 {%0,%1,%2,%3}, [%4];"
        : "=r"(r[0]), "=r"(r[1]), "=r"(r[2]), "=r"(r[3]) : "r"(addr));
}

__device__ __forceinline__ void mma16(float* d, const uint32_t* a, const uint32_t* b) {
    asm volatile(
        "mma.sync.aligned.m16n8k16.row.col.f32.f16.f16.f32 "
        "{%0,%1,%2,%3}, {%4,%5,%6,%7}, {%8,%9}, {%0,%1,%2,%3};"
        : "+f"(d[0]), "+f"(d[1]), "+f"(d[2]), "+f"(d[3])
        : "r"(a[0]), "r"(a[1]), "r"(a[2]), "r"(a[3]), "r"(b[0]), "r"(b[1]));
}

// ---- split x to fp16 h/l and transpose NCHW -> NHWC ----
__global__ __launch_bounds__(256)
void split_x_kernel(const float* __restrict__ x) {
    __shared__ float tile[64 * 129];
    const int b = blockIdx.x >> 7;
    const int y = blockIdx.x & 127;
    const int tid = threadIdx.x;

    for (int i = 0; i < 32; i++) {
        const int idx = i * 256 + tid;
        const int ci = idx >> 7, xx = idx & 127;
        tile[ci * 129 + xx] = x[(((b * 64 + ci) << 7) + y << 7) + xx];
    }
    __syncthreads();
    for (int i = 0; i < 32; i++) {
        const int idx = i * 256 + tid;
        const int ci = idx & 63, xx = idx >> 6;
        const float v = tile[ci * 129 + xx];
        const __half h = __float2half(v);
        const __half l = __float2half(v - __half2float(h));
        const int o = (((b << 7) + y << 7) + xx << 6) + ci;
        g_xh16[o] = h;
        g_xl16[o] = l;
    }
}

// ---- prep weights: [tap][n][ci], scaled x16, fp16 h/l split ----
__global__ __launch_bounds__(256)
void prep_w_kernel(const float* __restrict__ Ws, const float* __restrict__ bs,
                   const float* __restrict__ Wx, const float* __restrict__ bx,
                   const float* __restrict__ Wy, const float* __restrict__ by) {
    const int idx = blockIdx.x * blockDim.x + threadIdx.x;
    if (idx < 9 * NOUT * 64) {
        const int tap = idx / (NOUT * 64);
        const int rem = idx - tap * (NOUT * 64);
        const int n = rem >> 6, ci = rem & 63;
        const int set = n >> 6, co = n & 63;
        const float* Wt = (set == 0) ? Ws : ((set == 1) ? Wx : Wy);
        const float w = Wt[(co * 64 + ci) * 9 + tap] * WSCALE;
        const __half h = __float2half(w);
        g_B16h[idx] = h;
        g_B16l[idx] = __float2half(w - __half2float(h));
    }
    if (idx < NOUT) {
        const int set = idx >> 6, co = idx & 63;
        const float* Bt = (set == 0) ? bs : ((set == 1) ? bx : by);
        g_bias[idx] = Bt[co];
    }
}

// ---- conv GEMM: CTA = (b, y). M=128 px, N=192 ch, K = 9 taps x 64 ci ----
__global__ __launch_bounds__(256, 1)
void conv_mma_kernel() {
    extern __shared__ __half smem[];
    const uint32_t sb = smem_addr(smem);
    const int tid = threadIdx.x;
    const int wid = tid >> 5;
    const int lane = tid & 31;
    const int b = blockIdx.x >> 7;
    const int y = blockIdx.x & 127;

    const int mbase = (wid >> 2) * 64;
    const int nbase = (wid & 3) * 48;

    // ldmatrix lane addressing
    const int a_row16 = lane & 15;
    const int a_kh    = (lane >> 4) * 8;          // k half-select for A
    const int b_ntp   = (lane >> 4) * 8;          // n sub-tile within pair
    const int b_kh    = ((lane >> 3) & 1) * 8;
    const int b_row   = lane & 7;

    float acc[4][6][4];
    #pragma unroll
    for (int mt = 0; mt < 4; mt++)
        #pragma unroll
        for (int nt = 0; nt < 6; nt++)
            #pragma unroll
            for (int r = 0; r < 4; r++) acc[mt][nt][r] = 0.0f;

    // ---- prefetch B tap 0 into buf 0 via cp.async ----
    #pragma unroll
    for (int it = 0; it < 6; it++) {
        const int idx = it * 256 + tid;
        const int n = idx >> 3, ci8 = idx & 7;
        const int go = (n << 6) + ci8 * 8;
        const uint32_t so = sb + (uint32_t)(OFF_B + n * ARS + ci8 * 8) * 2;
        CP_ASYNC16(so,           (const char*)&g_B16h[go]);
        CP_ASYNC16(so + BTS * 2, (const char*)&g_B16l[go]);
    }
    CP_COMMIT();

    // ---- stage A: 3 input rows (y-1..y+1), x_in -1..128 -> rows 0..129 ----
    #pragma unroll 1
    for (int idx = tid; idx < 3120; idx += 256) {
        const int dy = idx / 1040;
        const int rem = idx - dy * 1040;
        const int xr = rem >> 3;
        const int ci8 = rem & 7;
        const int y_in = y + dy - 1;
        const int x_in = xr - 1;
        float4 vh = make_float4(0.f, 0.f, 0.f, 0.f);
        float4 vl = vh;
        if ((unsigned)y_in < 128u && (unsigned)x_in < 128u) {
            const int o = ((((b << 7) + y_in << 7) + x_in) << 6) + ci8 * 8;
            vh = *(const float4*)&g_xh16[o];
            vl = *(const float4*)&g_xl16[o];
        }
        const int so = dy * APLN + xr * ARS + ci8 * 8;
        *(float4*)&smem[OFF_AH + so] = vh;
        *(float4*)&smem[OFF_AL + so] = vl;
    }

    CP_WAIT0();
    __syncthreads();

    #pragma unroll 1
    for (int tap = 0; tap < 9; tap++) {
        const int buf = tap & 1;

        // prefetch next tap's B into other buffer (async, overlaps mma below)
        if (tap < 8) {
            const int nb = (tap + 1) & 1;
            const int gbase = (tap + 1) * NOUT * 64;
            #pragma unroll
            for (int it = 0; it < 6; it++) {
                const int idx = it * 256 + tid;
                const int n = idx >> 3, ci8 = idx & 7;
                const int go = gbase + (n << 6) + ci8 * 8;
                const uint32_t so = sb + (uint32_t)(OFF_B + (nb * 2) * BTS + n * ARS + ci8 * 8) * 2;
                CP_ASYNC16(so,           (const char*)&g_B16h[go]);
                CP_ASYNC16(so + BTS * 2, (const char*)&g_B16l[go]);
            }
            CP_COMMIT();
        }

        const int dy = tap / 3;
        const int dx = tap - dy * 3;

        const uint32_t aBaseH = sb + (uint32_t)(OFF_AH + dy * APLN
                              + (mbase + a_row16 + dx) * ARS + a_kh) * 2;
        const uint32_t aBaseL = aBaseH + (uint32_t)(OFF_AL - OFF_AH) * 2;
        const uint32_t bBaseH = sb + (uint32_t)(OFF_B + (buf * 2) * BTS
                              + (nbase + b_ntp + b_row) * ARS + b_kh) * 2;
        const uint32_t bBaseL = bBaseH + (uint32_t)(BTS) * 2;

        #pragma unroll
        for (int ks = 0; ks < 4; ks++) {
            const uint32_t ko = (uint32_t)ks * 32;   // 16 halves
            uint32_t Ah[4][4], Al[4][4], Bh[3][4], Bl[3][4];
            #pragma unroll
            for (int mt = 0; mt < 4; mt++) {
                ldsm_x4(Ah[mt], aBaseH + (uint32_t)(mt * 16 * ARS) * 2 + ko);
                ldsm_x4(Al[mt], aBaseL + (uint32_t)(mt * 16 * ARS) * 2 + ko);
            }
            #pragma unroll
            for (int p = 0; p < 3; p++) {
                ldsm_x4(Bh[p], bBaseH + (uint32_t)(p * 16 * ARS) * 2 + ko);
                ldsm_x4(Bl[p], bBaseL + (uint32_t)(p * 16 * ARS) * 2 + ko);
            }
            #pragma unroll
            for (int mt = 0; mt < 4; mt++)
                #pragma unroll
                for (int nt = 0; nt < 6; nt++)
                    mma16(acc[mt][nt], Ah[mt], &Bh[nt >> 1][(nt & 1) * 2]);
            #pragma unroll
            for (int mt = 0; mt < 4; mt++)
                #pragma unroll
                for (int nt = 0; nt < 6; nt++)
                    mma16(acc[mt][nt], Ah[mt], &Bl[nt >> 1][(nt & 1) * 2]);
            #pragma unroll
            for (int mt = 0; mt < 4; mt++)
                #pragma unroll
                for (int nt = 0; nt < 6; nt++)
                    mma16(acc[mt][nt], Al[mt], &Bh[nt >> 1][(nt & 1) * 2]);
        }

        CP_WAIT0();
        __syncthreads();
    }

    // ---- epilogue: unscale, add bias, scattered stores ----
    const int lr = lane >> 2;
    const int lc = lane & 3;
    #pragma unroll
    for (int nt = 0; nt < 6; nt++) {
        const int n0 = nbase + nt * 8 + 2 * lc;
        const int set0 = n0 >> 6, co0 = n0 & 63;
        const int set1 = (n0 + 1) >> 6, co1 = (n0 + 1) & 63;
        float* op0 = (set0 == 0) ? g_score : ((set0 == 1) ? g_gx : g_gy);
        float* op1 = (set1 == 0) ? g_score : ((set1 == 1) ? g_gx : g_gy);
        const float bias0 = __ldg(&g_bias[n0]);
        const float bias1 = __ldg(&g_bias[n0 + 1]);
        #pragma unroll
        for (int mt = 0; mt < 4; mt++) {
            const int m0 = mbase + mt * 16 + lr;
            const int a0 = ((b * 64 + co0) << 14) + (y << 7);
            const int a1 = ((b * 64 + co1) << 14) + (y << 7);
            op0[a0 + m0]     = acc[mt][nt][0] * WSCALE_INV + bias0;
            op1[a1 + m0]     = acc[mt][nt][1] * WSCALE_INV + bias1;
            op0[a0 + m0 + 8] = acc[mt][nt][2] * WSCALE_INV + bias0;
            op1[a1 + m0 + 8] = acc[mt][nt][3] * WSCALE_INV + bias1;
        }
    }
}

// ---- bilinear grid sample (align_corners=False, zeros padding) ----
__global__ void sample_kernel(float* __restrict__ out) {
    const int idx = blockIdx.x * blockDim.x + threadIdx.x;
    if (idx >= NTOT) return;
    const int n = idx >> 14;

    const float gx = g_gx[idx];
    const float gy = g_gy[idx];
    const float ix = ((gx + 1.0f) * (float)W_ - 1.0f) * 0.5f;
    const float iy = ((gy + 1.0f) * (float)H_ - 1.0f) * 0.5f;

    const float x0f = floorf(ix);
    const float y0f = floorf(iy);
    const int ix0 = (int)x0f, iy0 = (int)y0f;
    const int ix1 = ix0 + 1, iy1 = iy0 + 1;
    const float wx1 = ix - x0f, wy1 = iy - y0f;
    const float wx0 = 1.0f - wx1, wy0 = 1.0f - wy1;

    const float* img = g_score + ((size_t)n << 14);
    float v = 0.0f;
    if ((unsigned)iy0 < H_ && (unsigned)ix0 < W_) v = fmaf(__ldg(&img[iy0 * W_ + ix0]), wy0 * wx0, v);
    if ((unsigned)iy0 < H_ && (unsigned)ix1 < W_) v = fmaf(__ldg(&img[iy0 * W_ + ix1]), wy0 * wx1, v);
    if ((unsigned)iy1 < H_ && (unsigned)ix0 < W_) v = fmaf(__ldg(&img[iy1 * W_ + ix0]), wy1 * wx0, v);
    if ((unsigned)iy1 < H_ && (unsigned)ix1 < W_) v = fmaf(__ldg(&img[iy1 * W_ + ix1]), wy1 * wx1, v);

    out[idx] = v;
}

extern "C" void kernel_launch(void* const* d_in, const int* in_sizes, int n_in,
                              void* d_out, int out_size) {
    const float* x  = (const float*)d_in[0];
    const float* Ws = (const float*)d_in[1];
    const float* bs = (const float*)d_in[2];
    const float* Wx = (const float*)d_in[3];
    const float* bx = (const float*)d_in[4];
    const float* Wy = (const float*)d_in[5];
    const float* by = (const float*)d_in[6];
    float* out = (float*)d_out;

    cudaFuncSetAttribute(conv_mma_kernel,
                         cudaFuncAttributeMaxDynamicSharedMemorySize, SMEM_BYTES);

    split_x_kernel<<<B_ * H_, 256>>>(x);
    prep_w_kernel<<<(9 * NOUT * 64 + 255) / 256, 256>>>(Ws, bs, Wx, bx, Wy, by);
    conv_mma_kernel<<<B_ * H_, 256, SMEM_BYTES>>>();
    sample_kernel<<<(NTOT + 255) / 256, 256>>>(out);
}

// round 8
// speedup vs baseline: 4.3880x; 1.0015x over previous
#include <cuda_runtime.h>
#include <cuda_fp16.h>
#include <cstdint>

#define B_ 16
#define C_ 64
#define H_ 128
#define W_ 128
#define NTOT (B_*C_*H_*W_)
#define NOUT 192
#define WSCALE 16.0f
#define WSCALE_INV 0.0625f

// ---- scratch (allocation-free rule: __device__ globals) ----
__device__ float  g_score[NTOT];
__device__ float  g_gx[NTOT];
__device__ float  g_gy[NTOT];
__device__ __half g_xh16[NTOT];          // NHWC: [b][y][x][ci]
__device__ __half g_xl16[NTOT];
__device__ __half g_B16h[9 * NOUT * 64]; // [tap][n][ci], scaled x16
__device__ __half g_B16l[9 * NOUT * 64];
__device__ float  g_bias[NOUT];

// ---- conv smem layout (halves) ----
#define ARS   72
#define APLN  (132 * ARS)
#define OFF_AH 0
#define OFF_AL (3 * APLN)
#define OFF_B  (6 * APLN)
#define BTS    (NOUT * 72)
#define SMEM_HALVES (OFF_B + 4 * BTS)     /* 112320 halves = 224640 B */
#define SMEM_BYTES  (SMEM_HALVES * 2)
// epilogue float buffer aliases the A region: [NOUT][132] floats = 101376 B
#define EP_STRIDE 132

__device__ __forceinline__ uint32_t smem_addr(const void* p) {
    return (uint32_t)__cvta_generic_to_shared(p);
}

#define CP_ASYNC16(dst, src) \
    asm volatile("cp.async.cg.shared.global [%0], [%1], 16;" :: "r"(dst), "l"(src) : "memory")
#define CP_COMMIT() asm volatile("cp.async.commit_group;" ::: "memory")
#define CP_WAIT0()  asm volatile("cp.async.wait_group 0;" ::: "memory")

__device__ __forceinline__ void ldsm_x4(uint32_t* r, uint32_t addr) {
    asm volatile("ldmatrix.sync.aligned.m8n8.x4.shared.b16 {%0,%1,%2,%3}, [%4];"
        : "=r"(r[0]), "=r"(r[1]), "=r"(r[2]), "=r"(r[3]) : "r"(addr));
}

__device__ __forceinline__ void mma16(float* d, const uint32_t* a, const uint32_t* b) {
    asm volatile(
        "mma.sync.aligned.m16n8k16.row.col.f32.f16.f16.f32 "
        "{%0,%1,%2,%3}, {%4,%5,%6,%7}, {%8,%9}, {%0,%1,%2,%3};"
        : "+f"(d[0]), "+f"(d[1]), "+f"(d[2]), "+f"(d[3])
        : "r"(a[0]), "r"(a[1]), "r"(a[2]), "r"(a[3]), "r"(b[0]), "r"(b[1]));
}

// ---- split x to fp16 h/l and transpose NCHW -> NHWC ----
__global__ __launch_bounds__(256)
void split_x_kernel(const float* __restrict__ x) {
    __shared__ float tile[64 * 129];
    const int b = blockIdx.x >> 7;
    const int y = blockIdx.x & 127;
    const int tid = threadIdx.x;

    for (int i = 0; i < 32; i++) {
        const int idx = i * 256 + tid;
        const int ci = idx >> 7, xx = idx & 127;
        tile[ci * 129 + xx] = x[(((b * 64 + ci) << 7) + y << 7) + xx];
    }
    __syncthreads();
    for (int i = 0; i < 32; i++) {
        const int idx = i * 256 + tid;
        const int ci = idx & 63, xx = idx >> 6;
        const float v = tile[ci * 129 + xx];
        const __half h = __float2half(v);
        const __half l = __float2half(v - __half2float(h));
        const int o = (((b << 7) + y << 7) + xx << 6) + ci;
        g_xh16[o] = h;
        g_xl16[o] = l;
    }
}

// ---- prep weights: [tap][n][ci], scaled x16, fp16 h/l split ----
__global__ __launch_bounds__(256)
void prep_w_kernel(const float* __restrict__ Ws, const float* __restrict__ bs,
                   const float* __restrict__ Wx, const float* __restrict__ bx,
                   const float* __restrict__ Wy, const float* __restrict__ by) {
    const int idx = blockIdx.x * blockDim.x + threadIdx.x;
    if (idx < 9 * NOUT * 64) {
        const int tap = idx / (NOUT * 64);
        const int rem = idx - tap * (NOUT * 64);
        const int n = rem >> 6, ci = rem & 63;
        const int set = n >> 6, co = n & 63;
        const float* Wt = (set == 0) ? Ws : ((set == 1) ? Wx : Wy);
        const float w = Wt[(co * 64 + ci) * 9 + tap] * WSCALE;
        const __half h = __float2half(w);
        g_B16h[idx] = h;
        g_B16l[idx] = __float2half(w - __half2float(h));
    }
    if (idx < NOUT) {
        const int set = idx >> 6, co = idx & 63;
        const float* Bt = (set == 0) ? bs : ((set == 1) ? bx : by);
        g_bias[idx] = Bt[co];
    }
}

// ---- conv GEMM: CTA = (b, y). 512 thr, warp grid 4m x 4n, warp tile 32x48 ----
__global__ __launch_bounds__(512, 1)
void conv_mma_kernel() {
    extern __shared__ __half smem[];
    float* s_out = (float*)smem;          // aliases A region in epilogue
    const uint32_t sb = smem_addr(smem);
    const int tid = threadIdx.x;
    const int wid = tid >> 5;
    const int lane = tid & 31;
    const int b = blockIdx.x >> 7;
    const int y = blockIdx.x & 127;

    const int mbase = (wid & 3) * 32;
    const int nbase = (wid >> 2) * 48;

    // ldmatrix lane addressing
    const int a_row16 = lane & 15;
    const int a_kh    = (lane >> 4) * 8;
    const int b_ntp   = (lane >> 4) * 8;
    const int b_kh    = ((lane >> 3) & 1) * 8;
    const int b_row   = lane & 7;

    float acc[2][6][4];
    #pragma unroll
    for (int mt = 0; mt < 2; mt++)
        #pragma unroll
        for (int nt = 0; nt < 6; nt++)
            #pragma unroll
            for (int r = 0; r < 4; r++) acc[mt][nt][r] = 0.0f;

    // ---- prefetch B tap 0 into buf 0 via cp.async (1536 chunks / 512 thr) ----
    #pragma unroll
    for (int it = 0; it < 3; it++) {
        const int idx = it * 512 + tid;
        const int n = idx >> 3, ci8 = idx & 7;
        const int go = (n << 6) + ci8 * 8;
        const uint32_t so = sb + (uint32_t)(OFF_B + n * 72 + ci8 * 8) * 2;
        CP_ASYNC16(so,           (const char*)&g_B16h[go]);
        CP_ASYNC16(so + BTS * 2, (const char*)&g_B16l[go]);
    }
    CP_COMMIT();

    // ---- stage A: 3 input rows (y-1..y+1), x_in -1..128 -> rows 0..129 ----
    #pragma unroll 1
    for (int idx = tid; idx < 3120; idx += 512) {
        const int dy = idx / 1040;
        const int rem = idx - dy * 1040;
        const int xr = rem >> 3;
        const int ci8 = rem & 7;
        const int y_in = y + dy - 1;
        const int x_in = xr - 1;
        float4 vh = make_float4(0.f, 0.f, 0.f, 0.f);
        float4 vl = vh;
        if ((unsigned)y_in < 128u && (unsigned)x_in < 128u) {
            const int o = ((((b << 7) + y_in << 7) + x_in) << 6) + ci8 * 8;
            vh = *(const float4*)&g_xh16[o];
            vl = *(const float4*)&g_xl16[o];
        }
        const int so = dy * APLN + xr * ARS + ci8 * 8;
        *(float4*)&smem[OFF_AH + so] = vh;
        *(float4*)&smem[OFF_AL + so] = vl;
    }

    CP_WAIT0();
    __syncthreads();

    #pragma unroll 1
    for (int tap = 0; tap < 9; tap++) {
        const int buf = tap & 1;

        if (tap < 8) {
            const int nb = (tap + 1) & 1;
            const int gbase = (tap + 1) * NOUT * 64;
            #pragma unroll
            for (int it = 0; it < 3; it++) {
                const int idx = it * 512 + tid;
                const int n = idx >> 3, ci8 = idx & 7;
                const int go = gbase + (n << 6) + ci8 * 8;
                const uint32_t so = sb + (uint32_t)(OFF_B + (nb * 2) * BTS + n * 72 + ci8 * 8) * 2;
                CP_ASYNC16(so,           (const char*)&g_B16h[go]);
                CP_ASYNC16(so + BTS * 2, (const char*)&g_B16l[go]);
            }
            CP_COMMIT();
        }

        const int dy = tap / 3;
        const int dx = tap - dy * 3;

        const uint32_t aBaseH = sb + (uint32_t)(OFF_AH + dy * APLN
                              + (mbase + a_row16 + dx) * ARS + a_kh) * 2;
        const uint32_t aBaseL = aBaseH + (uint32_t)(OFF_AL - OFF_AH) * 2;
        const uint32_t bBaseH = sb + (uint32_t)(OFF_B + (buf * 2) * BTS
                              + (nbase + b_ntp + b_row) * 72 + b_kh) * 2;
        const uint32_t bBaseL = bBaseH + (uint32_t)(BTS) * 2;

        #pragma unroll
        for (int ks = 0; ks < 4; ks++) {
            const uint32_t ko = (uint32_t)ks * 32;
            uint32_t Ah[2][4], Al[2][4], Bh[3][4], Bl[3][4];
            #pragma unroll
            for (int mt = 0; mt < 2; mt++) {
                ldsm_x4(Ah[mt], aBaseH + (uint32_t)(mt * 16 * ARS) * 2 + ko);
                ldsm_x4(Al[mt], aBaseL + (uint32_t)(mt * 16 * ARS) * 2 + ko);
            }
            #pragma unroll
            for (int p = 0; p < 3; p++) {
                ldsm_x4(Bh[p], bBaseH + (uint32_t)(p * 16 * 72) * 2 + ko);
                ldsm_x4(Bl[p], bBaseL + (uint32_t)(p * 16 * 72) * 2 + ko);
            }
            #pragma unroll
            for (int mt = 0; mt < 2; mt++)
                #pragma unroll
                for (int nt = 0; nt < 6; nt++)
                    mma16(acc[mt][nt], Ah[mt], &Bh[nt >> 1][(nt & 1) * 2]);
            #pragma unroll
            for (int mt = 0; mt < 2; mt++)
                #pragma unroll
                for (int nt = 0; nt < 6; nt++)
                    mma16(acc[mt][nt], Ah[mt], &Bl[nt >> 1][(nt & 1) * 2]);
            #pragma unroll
            for (int mt = 0; mt < 2; mt++)
                #pragma unroll
                for (int nt = 0; nt < 6; nt++)
                    mma16(acc[mt][nt], Al[mt], &Bh[nt >> 1][(nt & 1) * 2]);
        }

        CP_WAIT0();
        __syncthreads();
    }

    // ---- epilogue: transpose through smem, then coalesced float4 stores ----
    const int lr = lane >> 2;
    const int lc = lane & 3;
    // stage accumulators into s_out[n][m] (stride 132 -> conflict-free)
    #pragma unroll
    for (int nt = 0; nt < 6; nt++) {
        const int n0 = nbase + nt * 8 + 2 * lc;
        #pragma unroll
        for (int mt = 0; mt < 2; mt++) {
            const int m0 = mbase + mt * 16 + lr;
            s_out[n0 * EP_STRIDE + m0]           = acc[mt][nt][0];
            s_out[(n0 + 1) * EP_STRIDE + m0]     = acc[mt][nt][1];
            s_out[n0 * EP_STRIDE + m0 + 8]       = acc[mt][nt][2];
            s_out[(n0 + 1) * EP_STRIDE + m0 + 8] = acc[mt][nt][3];
        }
    }
    __syncthreads();

    // readout: 192 rows x 32 float4, coalesced STG.128
    #pragma unroll 1
    for (int it = 0; it < 12; it++) {
        const int idx = it * 512 + tid;
        const int n = idx >> 5;
        const int m4 = idx & 31;
        const int set = n >> 6, co = n & 63;
        float* op = (set == 0) ? g_score : ((set == 1) ? g_gx : g_gy);
        const float bias = __ldg(&g_bias[n]);
        float4 v = *(const float4*)&s_out[n * EP_STRIDE + m4 * 4];
        v.x = fmaf(v.x, WSCALE_INV, bias);
        v.y = fmaf(v.y, WSCALE_INV, bias);
        v.z = fmaf(v.z, WSCALE_INV, bias);
        v.w = fmaf(v.w, WSCALE_INV, bias);
        *(float4*)&op[((b * 64 + co) << 14) + (y << 7) + m4 * 4] = v;
    }
}

// ---- bilinear grid sample (align_corners=False, zeros padding) ----
__global__ void sample_kernel(float* __restrict__ out) {
    const int idx = blockIdx.x * blockDim.x + threadIdx.x;
    if (idx >= NTOT) return;
    const int n = idx >> 14;

    const float gx = g_gx[idx];
    const float gy = g_gy[idx];
    const float ix = ((gx + 1.0f) * (float)W_ - 1.0f) * 0.5f;
    const float iy = ((gy + 1.0f) * (float)H_ - 1.0f) * 0.5f;

    const float x0f = floorf(ix);
    const float y0f = floorf(iy);
    const int ix0 = (int)x0f, iy0 = (int)y0f;
    const int ix1 = ix0 + 1, iy1 = iy0 + 1;
    const float wx1 = ix - x0f, wy1 = iy - y0f;
    const float wx0 = 1.0f - wx1, wy0 = 1.0f - wy1;

    const float* img = g_score + ((size_t)n << 14);
    float v = 0.0f;
    if ((unsigned)iy0 < H_ && (unsigned)ix0 < W_) v = fmaf(__ldg(&img[iy0 * W_ + ix0]), wy0 * wx0, v);
    if ((unsigned)iy0 < H_ && (unsigned)ix1 < W_) v = fmaf(__ldg(&img[iy0 * W_ + ix1]), wy0 * wx1, v);
    if ((unsigned)iy1 < H_ && (unsigned)ix0 < W_) v = fmaf(__ldg(&img[iy1 * W_ + ix0]), wy1 * wx0, v);
    if ((unsigned)iy1 < H_ && (unsigned)ix1 < W_) v = fmaf(__ldg(&img[iy1 * W_ + ix1]), wy1 * wx1, v);

    out[idx] = v;
}

extern "C" void kernel_launch(void* const* d_in, const int* in_sizes, int n_in,
                              void* d_out, int out_size) {
    const float* x  = (const float*)d_in[0];
    const float* Ws = (const float*)d_in[1];
    const float* bs = (const float*)d_in[2];
    const float* Wx = (const float*)d_in[3];
    const float* bx = (const float*)d_in[4];
    const float* Wy = (const float*)d_in[5];
    const float* by = (const float*)d_in[6];
    float* out = (float*)d_out;

    cudaFuncSetAttribute(conv_mma_kernel,
                         cudaFuncAttributeMaxDynamicSharedMemorySize, SMEM_BYTES);

    split_x_kernel<<<B_ * H_, 256>>>(x);
    prep_w_kernel<<<(9 * NOUT * 64 + 255) / 256, 256>>>(Ws, bs, Wx, bx, Wy, by);
    conv_mma_kernel<<<B_ * H_, 512, SMEM_BYTES>>>();
    sample_kernel<<<(NTOT + 255) / 256, 256>>>(out);
}